// round 14
// baseline (speedup 1.0000x reference)
#include <cuda_runtime.h>
#include <cuda_bf16.h>
#include <math.h>
#include <stdint.h>

#define NN 20000
#define EE 160000
#define ETOT (EE + NN)
#define HH 8
#define GG 128
#define DD 512
#define OUTD 128
#define SCAN_T 1024
#define SCAN_CH 20   // 1024*20 = 20480 >= 20000

// ---------------- scratch (device globals; no runtime allocation) -------------
__device__ float g_h[NN * DD];          // post-GEMM per-head features
__device__ float g_y[NN * DD];          // final-layer output (for pooling)
__device__ float g_es[NN * HH];
__device__ float g_ed[NN * HH];
__device__ int   g_cnt[NN];
__device__ int   g_off[NN + 1];
__device__ int   g_cur[NN];
__device__ int   g_srcl[ETOT];
__device__ int   g_gstart[GG];
__device__ int   g_gcnt[GG];
__device__ __nv_bfloat16 g_ahi[NN * DD];       // split-bf16 of layer input
__device__ __nv_bfloat16 g_alo[NN * DD];
__device__ __nv_bfloat16 g_wbhi[3 * DD * DD];  // W in bf16 [k][n] (hi/lo), 3 layers
__device__ __nv_bfloat16 g_wblo[3 * DD * DD];

#define SWZ(x)   ((uint32_t)(x) ^ ((((uint32_t)(x)) >> 3) & 0x70u))
#define SWZ64(x) ((uint32_t)(x) ^ ((((uint32_t)(x)) >> 3) & 0x30u))

__device__ __forceinline__ uint32_t smem_to_u32(const void* p) {
    uint32_t a;
    asm("{ .reg .u64 t; cvta.to.shared.u64 t, %1; cvt.u32.u64 %0, t; }"
        : "=r"(a) : "l"(p));
    return a;
}

__device__ __forceinline__ void cp_async16(uint32_t dst, const void* src) {
    asm volatile("cp.async.cg.shared.global [%0], [%1], 16;\n"
                 :: "r"(dst), "l"(src));
}

__device__ __forceinline__ void mma_bf16(float* c, const uint32_t* a,
                                         uint32_t b0, uint32_t b1) {
    asm volatile(
        "mma.sync.aligned.m16n8k16.row.col.f32.bf16.bf16.f32 "
        "{%0,%1,%2,%3}, {%4,%5,%6,%7}, {%8,%9}, {%0,%1,%2,%3};"
        : "+f"(c[0]), "+f"(c[1]), "+f"(c[2]), "+f"(c[3])
        : "r"(a[0]), "r"(a[1]), "r"(a[2]), "r"(a[3]), "r"(b0), "r"(b1));
}

// ---------------- CSR build ---------------------------------------------------
__global__ void k_init() {
    int t = blockIdx.x * blockDim.x + threadIdx.x;
    if (t < NN) g_cnt[t] = 0;
    if (t < GG) { g_gstart[t] = NN; g_gcnt[t] = 0; }
}

// fused: edge histogram + per-graph (start,count)
__global__ void k_countinfo(const int* __restrict__ ei, const int* __restrict__ batch) {
    int e = blockIdx.x * blockDim.x + threadIdx.x;
    if (e < ETOT) {
        int dst = (e < EE) ? ei[EE + e] : (e - EE);
        atomicAdd(&g_cnt[dst], 1);
    }
    if (e < NN) {
        int b = batch[e];
        atomicMin(&g_gstart[b], e);
        atomicAdd(&g_gcnt[b], 1);
    }
}

__global__ void k_scan() {
    __shared__ int ss[SCAN_T];
    int tid = threadIdx.x;
    int base = tid * SCAN_CH;
    int c[SCAN_CH];
    int local = 0;
#pragma unroll
    for (int i = 0; i < SCAN_CH; i++) {
        int idx = base + i;
        int v = (idx < NN) ? g_cnt[idx] : 0;
        c[i] = v; local += v;
    }
    ss[tid] = local; __syncthreads();
    for (int off = 1; off < SCAN_T; off <<= 1) {
        int v = (tid >= off) ? ss[tid - off] : 0;
        __syncthreads();
        ss[tid] += v;
        __syncthreads();
    }
    int run = ss[tid] - local;
#pragma unroll
    for (int i = 0; i < SCAN_CH; i++) {
        int idx = base + i;
        if (idx < NN) { g_off[idx] = run; g_cur[idx] = run; run += c[i]; }
    }
    if (tid == SCAN_T - 1) g_off[NN] = ss[SCAN_T - 1];
}

__global__ void k_fill(const int* __restrict__ ei) {
    int e = blockIdx.x * blockDim.x + threadIdx.x;
    if (e >= ETOT) return;
    int src, dst;
    if (e < EE) { src = ei[e]; dst = ei[EE + e]; }
    else        { src = dst = e - EE; }
    int p = atomicAdd(&g_cur[dst], 1);
    g_srcl[p] = src;
}

// ---------------- split-bf16 conversions -----------------------------------------
__global__ void k_split_a(const float* __restrict__ src) {
    int stride = gridDim.x * blockDim.x;
    for (int i = blockIdx.x * blockDim.x + threadIdx.x; i < NN * DD / 4; i += stride) {
        float4 v = ((const float4*)src)[i];
        __nv_bfloat16 h0 = __float2bfloat16_rn(v.x);
        __nv_bfloat16 h1 = __float2bfloat16_rn(v.y);
        __nv_bfloat16 h2 = __float2bfloat16_rn(v.z);
        __nv_bfloat16 h3 = __float2bfloat16_rn(v.w);
        __nv_bfloat16 l0 = __float2bfloat16_rn(v.x - __bfloat162float(h0));
        __nv_bfloat16 l1 = __float2bfloat16_rn(v.y - __bfloat162float(h1));
        __nv_bfloat16 l2 = __float2bfloat16_rn(v.z - __bfloat162float(h2));
        __nv_bfloat16 l3 = __float2bfloat16_rn(v.w - __bfloat162float(h3));
        ((__nv_bfloat162*)g_ahi)[i * 2]     = __nv_bfloat162(h0, h1);
        ((__nv_bfloat162*)g_ahi)[i * 2 + 1] = __nv_bfloat162(h2, h3);
        ((__nv_bfloat162*)g_alo)[i * 2]     = __nv_bfloat162(l0, l1);
        ((__nv_bfloat162*)g_alo)[i * 2 + 1] = __nv_bfloat162(l2, l3);
    }
}

__global__ void k_split_w3(const float* __restrict__ W0, const float* __restrict__ W1,
                           const float* __restrict__ W2) {
    int i = blockIdx.x * blockDim.x + threadIdx.x;
    if (i >= 3 * DD * DD) return;
    int l = i >> 18;                 // / (512*512)
    int r = i & (DD * DD - 1);
    const float* W = (l == 0) ? W0 : (l == 1) ? W1 : W2;
    float v = W[r];
    __nv_bfloat16 h = __float2bfloat16_rn(v);
    g_wbhi[i] = h;
    g_wblo[i] = __float2bfloat16_rn(v - __bfloat162float(h));
}

// ---------------- HMMA bf16 split GEMM + fused attention scores -----------------
// CTA tile 64x128, 128 threads (4 warps 2x2, warp tile 32x64 = one head wide).
// K-chunk = 32; stage = 24KB; 3 stages = 72KB -> 3 CTAs/SM. One barrier/chunk.
// MMA issue order is PASS-MAJOR across mi so same-accumulator reuse distance = 4.
#define MMA_SMEM (3 * 24576)
#define NCHUNK 16

__global__ __launch_bounds__(128, 3)
void k_mma(const float* __restrict__ as_, const float* __restrict__ ad_, int layer) {
    extern __shared__ __align__(128) char smem[];
    const uint32_t sbase = smem_to_u32(smem);
    const int tid = threadIdx.x, lane = tid & 31, warp = tid >> 5;
    const int m0 = blockIdx.y * 64, n0 = blockIdx.x * 128;
    const int m0w = (warp >> 1) * 32, wn = warp & 1;
    const __nv_bfloat16* wbh = g_wbhi + (size_t)layer * DD * DD;
    const __nv_bfloat16* wbl = g_wblo + (size_t)layer * DD * DD;

    float c[2][8][4];
#pragma unroll
    for (int mi = 0; mi < 2; mi++)
#pragma unroll
        for (int ni = 0; ni < 8; ni++)
#pragma unroll
            for (int q = 0; q < 4; q++) c[mi][ni][q] = 0.f;

    auto issue = [&](int cc) {
        int k0 = cc * 32;
        uint32_t base = sbase + (uint32_t)(cc % 3) * 24576u;
#pragma unroll
        for (int p = 0; p < 2; p++) {
            int i = tid + p * 128;          // [0,256): row=i>>2, u=i&3
            int row = i >> 2, u = i & 3;
            int gr = m0 + row; if (gr > NN - 1) gr = NN - 1;
            cp_async16(base + SWZ64(row * 64 + u * 16),
                       g_ahi + ((size_t)gr * DD + k0 + u * 8));
            cp_async16(base + 4096u + SWZ64(row * 64 + u * 16),
                       g_alo + ((size_t)gr * DD + k0 + u * 8));
        }
#pragma unroll
        for (int p = 0; p < 4; p++) {
            int i = tid + p * 128;          // [0,512): row=i>>4, u=i&15
            int row = i >> 4, u = i & 15;
            uint32_t hoff = (uint32_t)(u >> 3) * 4096u + SWZ(row * 128 + (u & 7) * 16);
            cp_async16(base + 8192u + hoff,
                       wbh + ((size_t)(k0 + row) * DD + n0 + u * 8));
            cp_async16(base + 16384u + hoff,
                       wbl + ((size_t)(k0 + row) * DD + n0 + u * 8));
        }
        asm volatile("cp.async.commit_group;" ::: "memory");
    };

    issue(0); issue(1);

    for (int cc = 0; cc < NCHUNK; cc++) {
        if (cc < NCHUNK - 1) asm volatile("cp.async.wait_group 1;" ::: "memory");
        else                 asm volatile("cp.async.wait_group 0;" ::: "memory");
        __syncthreads();

        uint32_t ah = sbase + (uint32_t)(cc % 3) * 24576u;
        uint32_t al = ah + 4096u;
        uint32_t wh = ah + 8192u  + (uint32_t)wn * 4096u;
        uint32_t wl = ah + 16384u + (uint32_t)wn * 4096u;

#pragma unroll
        for (int ks = 0; ks < 2; ks++) {
            uint32_t ahif[2][4], alof[2][4];
#pragma unroll
            for (int mi = 0; mi < 2; mi++) {
                int row = m0w + mi * 16 + (lane & 15);
                uint32_t off = SWZ64(row * 64 + ks * 32 + (lane >> 4) * 16);
                asm volatile(
                    "ldmatrix.sync.aligned.m8n8.x4.shared.b16 {%0,%1,%2,%3}, [%4];"
                    : "=r"(ahif[mi][0]), "=r"(ahif[mi][1]), "=r"(ahif[mi][2]), "=r"(ahif[mi][3])
                    : "r"(ah + off));
                asm volatile(
                    "ldmatrix.sync.aligned.m8n8.x4.shared.b16 {%0,%1,%2,%3}, [%4];"
                    : "=r"(alof[mi][0]), "=r"(alof[mi][1]), "=r"(alof[mi][2]), "=r"(alof[mi][3])
                    : "r"(al + off));
            }
#pragma unroll
            for (int j = 0; j < 4; j++) {
                int mat = lane >> 3;
                int rowb = ks * 16 + (mat & 1) * 8 + (lane & 7);
                int cb = j * 32 + (mat >> 1) * 16;
                uint32_t off = SWZ(rowb * 128 + cb);
                uint32_t bh[4], bl[4];
                asm volatile(
                    "ldmatrix.sync.aligned.m8n8.x4.trans.shared.b16 {%0,%1,%2,%3}, [%4];"
                    : "=r"(bh[0]), "=r"(bh[1]), "=r"(bh[2]), "=r"(bh[3]) : "r"(wh + off));
                asm volatile(
                    "ldmatrix.sync.aligned.m8n8.x4.trans.shared.b16 {%0,%1,%2,%3}, [%4];"
                    : "=r"(bl[0]), "=r"(bl[1]), "=r"(bl[2]), "=r"(bl[3]) : "r"(wl + off));
                // pass-major issue order: same-c reuse distance = 4 MMAs
                mma_bf16(c[0][2 * j],     ahif[0], bh[0], bh[1]);   // hi*hi
                mma_bf16(c[0][2 * j + 1], ahif[0], bh[2], bh[3]);
                mma_bf16(c[1][2 * j],     ahif[1], bh[0], bh[1]);
                mma_bf16(c[1][2 * j + 1], ahif[1], bh[2], bh[3]);
                mma_bf16(c[0][2 * j],     ahif[0], bl[0], bl[1]);   // hi*lo
                mma_bf16(c[0][2 * j + 1], ahif[0], bl[2], bl[3]);
                mma_bf16(c[1][2 * j],     ahif[1], bl[0], bl[1]);
                mma_bf16(c[1][2 * j + 1], ahif[1], bl[2], bl[3]);
                mma_bf16(c[0][2 * j],     alof[0], bh[0], bh[1]);   // lo*hi
                mma_bf16(c[0][2 * j + 1], alof[0], bh[2], bh[3]);
                mma_bf16(c[1][2 * j],     alof[1], bh[0], bh[1]);
                mma_bf16(c[1][2 * j + 1], alof[1], bh[2], bh[3]);
            }
        }
        if (cc + 2 < NCHUNK) issue(cc + 2);   // overwrites stage (cc-1)%3: safe
    }

    // ---------------- epilogue: store h + fused attention scores ----------------
    int g = lane >> 2, tg = lane & 3;
    int head = (n0 >> 6) + wn;                 // warp's 64-col span = one head
    const float* asv = as_ + head * 64;
    const float* adv = ad_ + head * 64;

#pragma unroll
    for (int mi = 0; mi < 2; mi++) {
        int r0 = m0 + m0w + mi * 16 + g;
        float es0 = 0.f, es1 = 0.f, ed0 = 0.f, ed1 = 0.f;
#pragma unroll
        for (int ni = 0; ni < 8; ni++) {
            int col = n0 + wn * 64 + ni * 8 + tg * 2;
            int off = ni * 8 + tg * 2;
            float a0 = asv[off], a1 = asv[off + 1];
            float d0 = adv[off], d1 = adv[off + 1];
            es0 += c[mi][ni][0] * a0 + c[mi][ni][1] * a1;
            es1 += c[mi][ni][2] * a0 + c[mi][ni][3] * a1;
            ed0 += c[mi][ni][0] * d0 + c[mi][ni][1] * d1;
            ed1 += c[mi][ni][2] * d0 + c[mi][ni][3] * d1;
            if (r0 < NN)
                *(float2*)&g_h[(size_t)r0 * DD + col] = make_float2(c[mi][ni][0], c[mi][ni][1]);
            if (r0 + 8 < NN)
                *(float2*)&g_h[(size_t)(r0 + 8) * DD + col] = make_float2(c[mi][ni][2], c[mi][ni][3]);
        }
#pragma unroll
        for (int o = 1; o <= 2; o <<= 1) {
            es0 += __shfl_xor_sync(0xffffffffu, es0, o);
            es1 += __shfl_xor_sync(0xffffffffu, es1, o);
            ed0 += __shfl_xor_sync(0xffffffffu, ed0, o);
            ed1 += __shfl_xor_sync(0xffffffffu, ed1, o);
        }
        if (tg == 0) {
            if (r0 < NN)     { g_es[r0 * 8 + head] = es0; g_ed[r0 * 8 + head] = ed0; }
            if (r0 + 8 < NN) { g_es[(r0 + 8) * 8 + head] = es1; g_ed[(r0 + 8) * 8 + head] = ed1; }
        }
    }
}

__device__ __forceinline__ float lrelu(float x) { return x > 0.f ? x : 0.2f * x; }

// ---------------- warp-per-node aggregate (no-max softmax, prefetched) ----------
// Single pass, no max tracking (scores bounded; shift-invariance). The next
// batch's srcl+es chain is prefetched BEFORE the current batch's gather so the
// two dependent L2 trips overlap the 16-wide gather latency.
__global__ __launch_bounds__(256)
void k_aggregate(const float* __restrict__ bias, const float* __restrict__ gamma,
                 const float* __restrict__ beta, int last) {
    const int warp = threadIdx.x >> 5;
    const int n = blockIdx.x * 8 + warp;           // grid = NN/8 exactly
    const int lane = threadIdx.x & 31;
    const int h8 = lane & 7;                       // head for score duty
    const int e4 = lane >> 3;                      // edge slot 0..3
    const int hp = lane >> 4;                      // head sub-offset for chunks

    int off0 = g_off[n];
    int deg  = g_off[n + 1] - off0;                // >= 1 (self-loop)
    float ed = g_ed[n * 8 + h8];

    float s = 0.f;
    float acc[4][4];
#pragma unroll
    for (int p = 0; p < 4; p++)
#pragma unroll
        for (int q = 0; q < 4; q++) acc[p][q] = 0.f;

    const float* hbase = g_h + (size_t)lane * 4;

    // prologue: prefetch batch 0 score chain
    int sc_next = 0; float ev_next = -1e30f;
    if (e4 < deg) {
        sc_next = g_srcl[off0 + e4];
        ev_next = g_es[sc_next * 8 + h8];
    }

    for (int base = 0; base < deg; base += 4) {
        int sc_my = sc_next;
        float t = (base + e4 < deg) ? __expf(lrelu(ev_next + ed)) : 0.f;

        // prefetch next batch's srcl->es chain before gathering
        int jn = base + 4 + e4;
        if (jn < deg) {
            sc_next = g_srcl[off0 + jn];
            ev_next = g_es[sc_next * 8 + h8];
        }

        s += t;
#pragma unroll
        for (int jj = 0; jj < 4; jj++) {
            int sc = __shfl_sync(0xffffffffu, sc_my, jj * 8);
            const float* row = hbase + (size_t)sc * DD;
#pragma unroll
            for (int p = 0; p < 4; p++) {
                float a = __shfl_sync(0xffffffffu, t, jj * 8 + p * 2 + hp);
                float4 v = *(const float4*)(row + p * 128);
                acc[p][0] += a * v.x; acc[p][1] += a * v.y;
                acc[p][2] += a * v.z; acc[p][3] += a * v.w;
            }
        }
    }
    // reduce s over the 4 edge slots (bits 3,4 of lane)
#pragma unroll
    for (int o = 8; o <= 16; o <<= 1) s += __shfl_xor_sync(0xffffffffu, s, o);
    float inv_s = 1.f / (s + 1e-16f);              // per head h8

    float sum = 0.f;
    float vals[4][4];
#pragma unroll
    for (int p = 0; p < 4; p++) {
        float is = __shfl_sync(0xffffffffu, inv_s, p * 2 + hp);
        float4 bb = *(const float4*)(bias + lane * 4 + p * 128);
        vals[p][0] = acc[p][0] * is + bb.x;
        vals[p][1] = acc[p][1] * is + bb.y;
        vals[p][2] = acc[p][2] * is + bb.z;
        vals[p][3] = acc[p][3] * is + bb.w;
        sum += vals[p][0] + vals[p][1] + vals[p][2] + vals[p][3];
    }
#pragma unroll
    for (int o = 16; o > 0; o >>= 1) sum += __shfl_xor_sync(0xffffffffu, sum, o);
    float mean = sum * (1.f / 512.f);

    float var = 0.f;
#pragma unroll
    for (int p = 0; p < 4; p++)
#pragma unroll
        for (int q = 0; q < 4; q++) { float d = vals[p][q] - mean; var += d * d; }
#pragma unroll
    for (int o = 16; o > 0; o >>= 1) var += __shfl_xor_sync(0xffffffffu, var, o);
    float rstd = rsqrtf(var * (1.f / 512.f) + 1e-5f);

#pragma unroll
    for (int p = 0; p < 4; p++) {
        float4 gv = *(const float4*)(gamma + lane * 4 + p * 128);
        float4 bv = *(const float4*)(beta + lane * 4 + p * 128);
        float o0 = fmaxf((vals[p][0] - mean) * rstd * gv.x + bv.x, 0.f);
        float o1 = fmaxf((vals[p][1] - mean) * rstd * gv.y + bv.y, 0.f);
        float o2 = fmaxf((vals[p][2] - mean) * rstd * gv.z + bv.z, 0.f);
        float o3 = fmaxf((vals[p][3] - mean) * rstd * gv.w + bv.w, 0.f);
        size_t doff = (size_t)n * DD + lane * 4 + p * 128;
        if (last) {
            *(float4*)(g_y + doff) = make_float4(o0, o1, o2, o3);
        } else {
            __nv_bfloat16 h0 = __float2bfloat16_rn(o0);
            __nv_bfloat16 h1 = __float2bfloat16_rn(o1);
            __nv_bfloat16 h2 = __float2bfloat16_rn(o2);
            __nv_bfloat16 h3 = __float2bfloat16_rn(o3);
            __nv_bfloat162 hp0(h0, h1), hp1(h2, h3);
            __nv_bfloat162 lp0(__float2bfloat16_rn(o0 - __bfloat162float(h0)),
                               __float2bfloat16_rn(o1 - __bfloat162float(h1)));
            __nv_bfloat162 lp1(__float2bfloat16_rn(o2 - __bfloat162float(h2)),
                               __float2bfloat16_rn(o3 - __bfloat162float(h3)));
            uint2 hw = make_uint2(*(uint32_t*)&hp0, *(uint32_t*)&hp1);
            uint2 lw = make_uint2(*(uint32_t*)&lp0, *(uint32_t*)&lp1);
            *(uint2*)(g_ahi + doff) = hw;
            *(uint2*)(g_alo + doff) = lw;
        }
    }
}

// ---------------- fused mean pool + FC per graph --------------------------------
__global__ void k_poolfc(const float* __restrict__ fcW, const float* __restrict__ fcb,
                         float* __restrict__ out) {
    __shared__ float sp[512];
    int g = blockIdx.x, tid = threadIdx.x;
    int cnt = g_gcnt[g];
    int start = g_gstart[g];
    const float4* y4 = (const float4*)g_y;
    float4 acc = make_float4(0.f, 0.f, 0.f, 0.f);
    for (int i = 0; i < cnt; i++) {
        float4 v = y4[(size_t)(start + i) * 128 + tid];
        acc.x += v.x; acc.y += v.y; acc.z += v.z; acc.w += v.w;
    }
    float sc = 1.f / (float)max(cnt, 1);
    sp[tid * 4 + 0] = acc.x * sc; sp[tid * 4 + 1] = acc.y * sc;
    sp[tid * 4 + 2] = acc.z * sc; sp[tid * 4 + 3] = acc.w * sc;
    __syncthreads();
    float r = fcb[tid];
#pragma unroll 8
    for (int k = 0; k < 512; k++) r += sp[k] * fcW[k * 128 + tid];
    out[g * 128 + tid] = r;
}

// ---------------- launcher -------------------------------------------------------
extern "C" void kernel_launch(void* const* d_in, const int* in_sizes, int n_in,
                              void* d_out, int out_size) {
    const float* x     = (const float*)d_in[0];
    const int*   ei    = (const int*)d_in[1];
    const int*   batch = (const int*)d_in[2];
    const float* W[3]  = {(const float*)d_in[3],  (const float*)d_in[9],  (const float*)d_in[15]};
    const float* as_[3]= {(const float*)d_in[4],  (const float*)d_in[10], (const float*)d_in[16]};
    const float* ad_[3]= {(const float*)d_in[5],  (const float*)d_in[11], (const float*)d_in[17]};
    const float* b_[3] = {(const float*)d_in[6],  (const float*)d_in[12], (const float*)d_in[18]};
    const float* gm_[3]= {(const float*)d_in[7],  (const float*)d_in[13], (const float*)d_in[19]};
    const float* be_[3]= {(const float*)d_in[8],  (const float*)d_in[14], (const float*)d_in[20]};
    const float* fcW = (const float*)d_in[21];
    const float* fcb = (const float*)d_in[22];
    float* out = (float*)d_out;

    // one-time infra (host resources only; graph topology identical every call)
    static cudaStream_t s2 = nullptr;
    static cudaEvent_t evF = nullptr, evW = nullptr, evC = nullptr;
    if (s2 == nullptr) {
        cudaStreamCreateWithFlags(&s2, cudaStreamNonBlocking);
        cudaEventCreateWithFlags(&evF, cudaEventDisableTiming);
        cudaEventCreateWithFlags(&evW, cudaEventDisableTiming);
        cudaEventCreateWithFlags(&evC, cudaEventDisableTiming);
        cudaFuncSetAttribute(k_mma, cudaFuncAttributeMaxDynamicSharedMemorySize, MMA_SMEM);
    }

    dim3 gemm_grid(4, (NN + 63) / 64);   // 4 x 313 = 1252 tiles

    // fork: side stream does W-split + CSR build concurrently with A-split + mma0
    cudaEventRecord(evF, 0);
    cudaStreamWaitEvent(s2, evF, 0);

    k_split_a<<<2560, 256>>>(x);                                        // main #1
    k_split_w3<<<(3 * DD * DD + 511) / 512, 512, 0, s2>>>(W[0], W[1], W[2]); // s2 #2
    cudaEventRecord(evW, s2);
    k_init<<<(NN + 255) / 256, 256, 0, s2>>>();                         // s2 #3
    cudaStreamWaitEvent(0, evW, 0);                 // mma0 needs W splits
    k_mma<<<gemm_grid, 128, MMA_SMEM>>>(as_[0], ad_[0], 0);             // main #4 <- profiled
    k_countinfo<<<(ETOT + 255) / 256, 256, 0, s2>>>(ei, batch);         // s2
    k_scan<<<1, SCAN_T, 0, s2>>>();                                     // s2
    k_fill<<<(ETOT + 255) / 256, 256, 0, s2>>>(ei);                     // s2
    cudaEventRecord(evC, s2);
    cudaStreamWaitEvent(0, evC, 0);                 // aggregate needs CSR

    k_aggregate<<<NN / 8, 256>>>(b_[0], gm_[0], be_[0], 0);

    for (int l = 1; l < 3; l++) {
        k_mma<<<gemm_grid, 128, MMA_SMEM>>>(as_[l], ad_[l], l);
        k_aggregate<<<NN / 8, 256>>>(b_[l], gm_[l], be_[l], l == 2 ? 1 : 0);
    }

    k_poolfc<<<GG, 128>>>(fcW, fcb, out);
}

// round 15
// speedup vs baseline: 1.0674x; 1.0674x over previous
#include <cuda_runtime.h>
#include <cuda_bf16.h>
#include <math.h>
#include <stdint.h>

#define NN 20000
#define EE 160000
#define ETOT (EE + NN)
#define HH 8
#define GG 128
#define DD 512
#define OUTD 128
#define SCAN_T 1024
#define SCAN_CH 20   // 1024*20 = 20480 >= 20000

// ---------------- scratch (device globals; no runtime allocation) -------------
__device__ float g_h[NN * DD];          // post-GEMM per-head features
__device__ float g_y[NN * DD];          // final-layer output (for pooling)
__device__ float g_es[NN * HH];
__device__ float g_ed[NN * HH];
__device__ int   g_cnt[NN];
__device__ int   g_off[NN + 1];
__device__ int   g_cur[NN];
__device__ int   g_srcl[ETOT];
__device__ int   g_gstart[GG];
__device__ int   g_gcnt[GG];
__device__ __nv_bfloat16 g_ahi[NN * DD];       // split-bf16 of layer input
__device__ __nv_bfloat16 g_alo[NN * DD];
__device__ __nv_bfloat16 g_wbhi[3 * DD * DD];  // W in bf16 [k][n] (hi/lo), 3 layers
__device__ __nv_bfloat16 g_wblo[3 * DD * DD];

#define SWZ(x)   ((uint32_t)(x) ^ ((((uint32_t)(x)) >> 3) & 0x70u))
#define SWZ64(x) ((uint32_t)(x) ^ ((((uint32_t)(x)) >> 3) & 0x30u))

__device__ __forceinline__ uint32_t smem_to_u32(const void* p) {
    uint32_t a;
    asm("{ .reg .u64 t; cvta.to.shared.u64 t, %1; cvt.u32.u64 %0, t; }"
        : "=r"(a) : "l"(p));
    return a;
}

__device__ __forceinline__ void cp_async16(uint32_t dst, const void* src) {
    asm volatile("cp.async.cg.shared.global [%0], [%1], 16;\n"
                 :: "r"(dst), "l"(src));
}

__device__ __forceinline__ void mma_bf16(float* c, const uint32_t* a,
                                         uint32_t b0, uint32_t b1) {
    asm volatile(
        "mma.sync.aligned.m16n8k16.row.col.f32.bf16.bf16.f32 "
        "{%0,%1,%2,%3}, {%4,%5,%6,%7}, {%8,%9}, {%0,%1,%2,%3};"
        : "+f"(c[0]), "+f"(c[1]), "+f"(c[2]), "+f"(c[3])
        : "r"(a[0]), "r"(a[1]), "r"(a[2]), "r"(a[3]), "r"(b0), "r"(b1));
}

// ---------------- CSR build ---------------------------------------------------
__global__ void k_init() {
    int t = blockIdx.x * blockDim.x + threadIdx.x;
    if (t < NN) g_cnt[t] = 0;
    if (t < GG) { g_gstart[t] = NN; g_gcnt[t] = 0; }
}

// fused: edge histogram + per-graph (start,count)
__global__ void k_countinfo(const int* __restrict__ ei, const int* __restrict__ batch) {
    int e = blockIdx.x * blockDim.x + threadIdx.x;
    if (e < ETOT) {
        int dst = (e < EE) ? ei[EE + e] : (e - EE);
        atomicAdd(&g_cnt[dst], 1);
    }
    if (e < NN) {
        int b = batch[e];
        atomicMin(&g_gstart[b], e);
        atomicAdd(&g_gcnt[b], 1);
    }
}

__global__ void k_scan() {
    __shared__ int ss[SCAN_T];
    int tid = threadIdx.x;
    int base = tid * SCAN_CH;
    int c[SCAN_CH];
    int local = 0;
#pragma unroll
    for (int i = 0; i < SCAN_CH; i++) {
        int idx = base + i;
        int v = (idx < NN) ? g_cnt[idx] : 0;
        c[i] = v; local += v;
    }
    ss[tid] = local; __syncthreads();
    for (int off = 1; off < SCAN_T; off <<= 1) {
        int v = (tid >= off) ? ss[tid - off] : 0;
        __syncthreads();
        ss[tid] += v;
        __syncthreads();
    }
    int run = ss[tid] - local;
#pragma unroll
    for (int i = 0; i < SCAN_CH; i++) {
        int idx = base + i;
        if (idx < NN) { g_off[idx] = run; g_cur[idx] = run; run += c[i]; }
    }
    if (tid == SCAN_T - 1) g_off[NN] = ss[SCAN_T - 1];
}

__global__ void k_fill(const int* __restrict__ ei) {
    int e = blockIdx.x * blockDim.x + threadIdx.x;
    if (e >= ETOT) return;
    int src, dst;
    if (e < EE) { src = ei[e]; dst = ei[EE + e]; }
    else        { src = dst = e - EE; }
    int p = atomicAdd(&g_cur[dst], 1);
    g_srcl[p] = src;
}

// ---------------- split-bf16 conversions -----------------------------------------
__global__ void k_split_a(const float* __restrict__ src) {
    int stride = gridDim.x * blockDim.x;
    for (int i = blockIdx.x * blockDim.x + threadIdx.x; i < NN * DD / 4; i += stride) {
        float4 v = ((const float4*)src)[i];
        __nv_bfloat16 h0 = __float2bfloat16_rn(v.x);
        __nv_bfloat16 h1 = __float2bfloat16_rn(v.y);
        __nv_bfloat16 h2 = __float2bfloat16_rn(v.z);
        __nv_bfloat16 h3 = __float2bfloat16_rn(v.w);
        __nv_bfloat16 l0 = __float2bfloat16_rn(v.x - __bfloat162float(h0));
        __nv_bfloat16 l1 = __float2bfloat16_rn(v.y - __bfloat162float(h1));
        __nv_bfloat16 l2 = __float2bfloat16_rn(v.z - __bfloat162float(h2));
        __nv_bfloat16 l3 = __float2bfloat16_rn(v.w - __bfloat162float(h3));
        ((__nv_bfloat162*)g_ahi)[i * 2]     = __nv_bfloat162(h0, h1);
        ((__nv_bfloat162*)g_ahi)[i * 2 + 1] = __nv_bfloat162(h2, h3);
        ((__nv_bfloat162*)g_alo)[i * 2]     = __nv_bfloat162(l0, l1);
        ((__nv_bfloat162*)g_alo)[i * 2 + 1] = __nv_bfloat162(l2, l3);
    }
}

__global__ void k_split_w3(const float* __restrict__ W0, const float* __restrict__ W1,
                           const float* __restrict__ W2) {
    int i = blockIdx.x * blockDim.x + threadIdx.x;
    if (i >= 3 * DD * DD) return;
    int l = i >> 18;                 // / (512*512)
    int r = i & (DD * DD - 1);
    const float* W = (l == 0) ? W0 : (l == 1) ? W1 : W2;
    float v = W[r];
    __nv_bfloat16 h = __float2bfloat16_rn(v);
    g_wbhi[i] = h;
    g_wblo[i] = __float2bfloat16_rn(v - __bfloat162float(h));
}

// ---------------- HMMA bf16 split GEMM + fused attention scores -----------------
// CTA tile 64x128, 128 threads (4 warps 2x2, warp tile 32x64 = one head wide).
// K-chunk = 32; stage = 24KB; 3 stages = 72KB -> 3 CTAs/SM. One barrier/chunk.
#define MMA_SMEM (3 * 24576)
#define NCHUNK 16

__global__ __launch_bounds__(128, 3)
void k_mma(const float* __restrict__ as_, const float* __restrict__ ad_, int layer) {
    extern __shared__ __align__(128) char smem[];
    const uint32_t sbase = smem_to_u32(smem);
    const int tid = threadIdx.x, lane = tid & 31, warp = tid >> 5;
    const int m0 = blockIdx.y * 64, n0 = blockIdx.x * 128;
    const int m0w = (warp >> 1) * 32, wn = warp & 1;
    const __nv_bfloat16* wbh = g_wbhi + (size_t)layer * DD * DD;
    const __nv_bfloat16* wbl = g_wblo + (size_t)layer * DD * DD;

    float c[2][8][4];
#pragma unroll
    for (int mi = 0; mi < 2; mi++)
#pragma unroll
        for (int ni = 0; ni < 8; ni++)
#pragma unroll
            for (int q = 0; q < 4; q++) c[mi][ni][q] = 0.f;

    auto issue = [&](int cc) {
        int k0 = cc * 32;
        uint32_t base = sbase + (uint32_t)(cc % 3) * 24576u;
#pragma unroll
        for (int p = 0; p < 2; p++) {
            int i = tid + p * 128;          // [0,256): row=i>>2, u=i&3
            int row = i >> 2, u = i & 3;
            int gr = m0 + row; if (gr > NN - 1) gr = NN - 1;
            cp_async16(base + SWZ64(row * 64 + u * 16),
                       g_ahi + ((size_t)gr * DD + k0 + u * 8));
            cp_async16(base + 4096u + SWZ64(row * 64 + u * 16),
                       g_alo + ((size_t)gr * DD + k0 + u * 8));
        }
#pragma unroll
        for (int p = 0; p < 4; p++) {
            int i = tid + p * 128;          // [0,512): row=i>>4, u=i&15
            int row = i >> 4, u = i & 15;
            uint32_t hoff = (uint32_t)(u >> 3) * 4096u + SWZ(row * 128 + (u & 7) * 16);
            cp_async16(base + 8192u + hoff,
                       wbh + ((size_t)(k0 + row) * DD + n0 + u * 8));
            cp_async16(base + 16384u + hoff,
                       wbl + ((size_t)(k0 + row) * DD + n0 + u * 8));
        }
        asm volatile("cp.async.commit_group;" ::: "memory");
    };

    issue(0); issue(1);

    for (int cc = 0; cc < NCHUNK; cc++) {
        if (cc < NCHUNK - 1) asm volatile("cp.async.wait_group 1;" ::: "memory");
        else                 asm volatile("cp.async.wait_group 0;" ::: "memory");
        __syncthreads();

        uint32_t ah = sbase + (uint32_t)(cc % 3) * 24576u;
        uint32_t al = ah + 4096u;
        uint32_t wh = ah + 8192u  + (uint32_t)wn * 4096u;
        uint32_t wl = ah + 16384u + (uint32_t)wn * 4096u;

#pragma unroll
        for (int ks = 0; ks < 2; ks++) {
            uint32_t ahif[2][4], alof[2][4];
#pragma unroll
            for (int mi = 0; mi < 2; mi++) {
                int row = m0w + mi * 16 + (lane & 15);
                uint32_t off = SWZ64(row * 64 + ks * 32 + (lane >> 4) * 16);
                asm volatile(
                    "ldmatrix.sync.aligned.m8n8.x4.shared.b16 {%0,%1,%2,%3}, [%4];"
                    : "=r"(ahif[mi][0]), "=r"(ahif[mi][1]), "=r"(ahif[mi][2]), "=r"(ahif[mi][3])
                    : "r"(ah + off));
                asm volatile(
                    "ldmatrix.sync.aligned.m8n8.x4.shared.b16 {%0,%1,%2,%3}, [%4];"
                    : "=r"(alof[mi][0]), "=r"(alof[mi][1]), "=r"(alof[mi][2]), "=r"(alof[mi][3])
                    : "r"(al + off));
            }
#pragma unroll
            for (int j = 0; j < 4; j++) {
                int mat = lane >> 3;
                int rowb = ks * 16 + (mat & 1) * 8 + (lane & 7);
                int cb = j * 32 + (mat >> 1) * 16;
                uint32_t off = SWZ(rowb * 128 + cb);
                uint32_t bh[4], bl[4];
                asm volatile(
                    "ldmatrix.sync.aligned.m8n8.x4.trans.shared.b16 {%0,%1,%2,%3}, [%4];"
                    : "=r"(bh[0]), "=r"(bh[1]), "=r"(bh[2]), "=r"(bh[3]) : "r"(wh + off));
                asm volatile(
                    "ldmatrix.sync.aligned.m8n8.x4.trans.shared.b16 {%0,%1,%2,%3}, [%4];"
                    : "=r"(bl[0]), "=r"(bl[1]), "=r"(bl[2]), "=r"(bl[3]) : "r"(wl + off));
#pragma unroll
                for (int mi = 0; mi < 2; mi++) {
                    mma_bf16(c[mi][2 * j],     ahif[mi], bh[0], bh[1]);   // hi*hi
                    mma_bf16(c[mi][2 * j + 1], ahif[mi], bh[2], bh[3]);
                    mma_bf16(c[mi][2 * j],     ahif[mi], bl[0], bl[1]);   // hi*lo
                    mma_bf16(c[mi][2 * j + 1], ahif[mi], bl[2], bl[3]);
                    mma_bf16(c[mi][2 * j],     alof[mi], bh[0], bh[1]);   // lo*hi
                    mma_bf16(c[mi][2 * j + 1], alof[mi], bh[2], bh[3]);
                }
            }
        }
        if (cc + 2 < NCHUNK) issue(cc + 2);   // overwrites stage (cc-1)%3: safe
    }

    // ---------------- epilogue: store h + fused attention scores ----------------
    int g = lane >> 2, tg = lane & 3;
    int head = (n0 >> 6) + wn;                 // warp's 64-col span = one head
    const float* asv = as_ + head * 64;
    const float* adv = ad_ + head * 64;

#pragma unroll
    for (int mi = 0; mi < 2; mi++) {
        int r0 = m0 + m0w + mi * 16 + g;
        float es0 = 0.f, es1 = 0.f, ed0 = 0.f, ed1 = 0.f;
#pragma unroll
        for (int ni = 0; ni < 8; ni++) {
            int col = n0 + wn * 64 + ni * 8 + tg * 2;
            int off = ni * 8 + tg * 2;
            float a0 = asv[off], a1 = asv[off + 1];
            float d0 = adv[off], d1 = adv[off + 1];
            es0 += c[mi][ni][0] * a0 + c[mi][ni][1] * a1;
            es1 += c[mi][ni][2] * a0 + c[mi][ni][3] * a1;
            ed0 += c[mi][ni][0] * d0 + c[mi][ni][1] * d1;
            ed1 += c[mi][ni][2] * d0 + c[mi][ni][3] * d1;
            if (r0 < NN)
                *(float2*)&g_h[(size_t)r0 * DD + col] = make_float2(c[mi][ni][0], c[mi][ni][1]);
            if (r0 + 8 < NN)
                *(float2*)&g_h[(size_t)(r0 + 8) * DD + col] = make_float2(c[mi][ni][2], c[mi][ni][3]);
        }
#pragma unroll
        for (int o = 1; o <= 2; o <<= 1) {
            es0 += __shfl_xor_sync(0xffffffffu, es0, o);
            es1 += __shfl_xor_sync(0xffffffffu, es1, o);
            ed0 += __shfl_xor_sync(0xffffffffu, ed0, o);
            ed1 += __shfl_xor_sync(0xffffffffu, ed1, o);
        }
        if (tg == 0) {
            if (r0 < NN)     { g_es[r0 * 8 + head] = es0; g_ed[r0 * 8 + head] = ed0; }
            if (r0 + 8 < NN) { g_es[(r0 + 8) * 8 + head] = es1; g_ed[(r0 + 8) * 8 + head] = ed1; }
        }
    }
}

__device__ __forceinline__ float lrelu(float x) { return x > 0.f ? x : 0.2f * x; }

// ---------------- warp-per-node aggregate (no-max softmax, 2-wide chain) --------
// 8 edges per iteration: both 4-edge sub-batches' srcl loads issue back-to-back,
// then both es loads — MLP=2 on the dependent score chain, straight-line code,
// no loop-carried prefetch state. Gather is the proven 4-edge shfl pattern x2.
__global__ __launch_bounds__(256)
void k_aggregate(const float* __restrict__ bias, const float* __restrict__ gamma,
                 const float* __restrict__ beta, int last) {
    const int warp = threadIdx.x >> 5;
    const int n = blockIdx.x * 8 + warp;           // grid = NN/8 exactly
    const int lane = threadIdx.x & 31;
    const int h8 = lane & 7;                       // head for score duty
    const int e4 = lane >> 3;                      // edge slot 0..3
    const int hp = lane >> 4;                      // head sub-offset for chunks

    int off0 = g_off[n];
    int deg  = g_off[n + 1] - off0;                // >= 1 (self-loop)
    float ed = g_ed[n * 8 + h8];

    float s = 0.f;
    float acc[4][4];
#pragma unroll
    for (int p = 0; p < 4; p++)
#pragma unroll
        for (int q = 0; q < 4; q++) acc[p][q] = 0.f;

    const float* hbase = g_h + (size_t)lane * 4;

    for (int base = 0; base < deg; base += 8) {
        int j0 = base + e4, j1 = base + 4 + e4;
        // two independent srcl loads, then two independent es loads (MLP=2)
        int sc0 = (j0 < deg) ? g_srcl[off0 + j0] : 0;
        int sc1 = (j1 < deg) ? g_srcl[off0 + j1] : 0;
        float ev0 = (j0 < deg) ? g_es[sc0 * 8 + h8] : 0.f;
        float ev1 = (j1 < deg) ? g_es[sc1 * 8 + h8] : 0.f;
        float t0 = (j0 < deg) ? __expf(lrelu(ev0 + ed)) : 0.f;
        float t1 = (j1 < deg) ? __expf(lrelu(ev1 + ed)) : 0.f;
        s += t0 + t1;

#pragma unroll
        for (int jj = 0; jj < 4; jj++) {
            int sc = __shfl_sync(0xffffffffu, sc0, jj * 8);
            const float* row = hbase + (size_t)sc * DD;
#pragma unroll
            for (int p = 0; p < 4; p++) {
                float a = __shfl_sync(0xffffffffu, t0, jj * 8 + p * 2 + hp);
                float4 v = *(const float4*)(row + p * 128);
                acc[p][0] += a * v.x; acc[p][1] += a * v.y;
                acc[p][2] += a * v.z; acc[p][3] += a * v.w;
            }
        }
        if (base + 4 < deg) {
#pragma unroll
            for (int jj = 0; jj < 4; jj++) {
                int sc = __shfl_sync(0xffffffffu, sc1, jj * 8);
                const float* row = hbase + (size_t)sc * DD;
#pragma unroll
                for (int p = 0; p < 4; p++) {
                    float a = __shfl_sync(0xffffffffu, t1, jj * 8 + p * 2 + hp);
                    float4 v = *(const float4*)(row + p * 128);
                    acc[p][0] += a * v.x; acc[p][1] += a * v.y;
                    acc[p][2] += a * v.z; acc[p][3] += a * v.w;
                }
            }
        }
    }
    // reduce s over the 4 edge slots (bits 3,4 of lane)
#pragma unroll
    for (int o = 8; o <= 16; o <<= 1) s += __shfl_xor_sync(0xffffffffu, s, o);
    float inv_s = 1.f / (s + 1e-16f);              // per head h8

    float sum = 0.f;
    float vals[4][4];
#pragma unroll
    for (int p = 0; p < 4; p++) {
        float is = __shfl_sync(0xffffffffu, inv_s, p * 2 + hp);
        float4 bb = *(const float4*)(bias + lane * 4 + p * 128);
        vals[p][0] = acc[p][0] * is + bb.x;
        vals[p][1] = acc[p][1] * is + bb.y;
        vals[p][2] = acc[p][2] * is + bb.z;
        vals[p][3] = acc[p][3] * is + bb.w;
        sum += vals[p][0] + vals[p][1] + vals[p][2] + vals[p][3];
    }
#pragma unroll
    for (int o = 16; o > 0; o >>= 1) sum += __shfl_xor_sync(0xffffffffu, sum, o);
    float mean = sum * (1.f / 512.f);

    float var = 0.f;
#pragma unroll
    for (int p = 0; p < 4; p++)
#pragma unroll
        for (int q = 0; q < 4; q++) { float d = vals[p][q] - mean; var += d * d; }
#pragma unroll
    for (int o = 16; o > 0; o >>= 1) var += __shfl_xor_sync(0xffffffffu, var, o);
    float rstd = rsqrtf(var * (1.f / 512.f) + 1e-5f);

#pragma unroll
    for (int p = 0; p < 4; p++) {
        float4 gv = *(const float4*)(gamma + lane * 4 + p * 128);
        float4 bv = *(const float4*)(beta + lane * 4 + p * 128);
        float o0 = fmaxf((vals[p][0] - mean) * rstd * gv.x + bv.x, 0.f);
        float o1 = fmaxf((vals[p][1] - mean) * rstd * gv.y + bv.y, 0.f);
        float o2 = fmaxf((vals[p][2] - mean) * rstd * gv.z + bv.z, 0.f);
        float o3 = fmaxf((vals[p][3] - mean) * rstd * gv.w + bv.w, 0.f);
        size_t doff = (size_t)n * DD + lane * 4 + p * 128;
        if (last) {
            *(float4*)(g_y + doff) = make_float4(o0, o1, o2, o3);
        } else {
            __nv_bfloat16 h0 = __float2bfloat16_rn(o0);
            __nv_bfloat16 h1 = __float2bfloat16_rn(o1);
            __nv_bfloat16 h2 = __float2bfloat16_rn(o2);
            __nv_bfloat16 h3 = __float2bfloat16_rn(o3);
            __nv_bfloat162 hp0(h0, h1), hp1(h2, h3);
            __nv_bfloat162 lp0(__float2bfloat16_rn(o0 - __bfloat162float(h0)),
                               __float2bfloat16_rn(o1 - __bfloat162float(h1)));
            __nv_bfloat162 lp1(__float2bfloat16_rn(o2 - __bfloat162float(h2)),
                               __float2bfloat16_rn(o3 - __bfloat162float(h3)));
            uint2 hw = make_uint2(*(uint32_t*)&hp0, *(uint32_t*)&hp1);
            uint2 lw = make_uint2(*(uint32_t*)&lp0, *(uint32_t*)&lp1);
            *(uint2*)(g_ahi + doff) = hw;
            *(uint2*)(g_alo + doff) = lw;
        }
    }
}

// ---------------- fused mean pool + FC per graph --------------------------------
__global__ void k_poolfc(const float* __restrict__ fcW, const float* __restrict__ fcb,
                         float* __restrict__ out) {
    __shared__ float sp[512];
    int g = blockIdx.x, tid = threadIdx.x;
    int cnt = g_gcnt[g];
    int start = g_gstart[g];
    const float4* y4 = (const float4*)g_y;
    float4 acc = make_float4(0.f, 0.f, 0.f, 0.f);
    for (int i = 0; i < cnt; i++) {
        float4 v = y4[(size_t)(start + i) * 128 + tid];
        acc.x += v.x; acc.y += v.y; acc.z += v.z; acc.w += v.w;
    }
    float sc = 1.f / (float)max(cnt, 1);
    sp[tid * 4 + 0] = acc.x * sc; sp[tid * 4 + 1] = acc.y * sc;
    sp[tid * 4 + 2] = acc.z * sc; sp[tid * 4 + 3] = acc.w * sc;
    __syncthreads();
    float r = fcb[tid];
#pragma unroll 8
    for (int k = 0; k < 512; k++) r += sp[k] * fcW[k * 128 + tid];
    out[g * 128 + tid] = r;
}

// ---------------- launcher -------------------------------------------------------
extern "C" void kernel_launch(void* const* d_in, const int* in_sizes, int n_in,
                              void* d_out, int out_size) {
    const float* x     = (const float*)d_in[0];
    const int*   ei    = (const int*)d_in[1];
    const int*   batch = (const int*)d_in[2];
    const float* W[3]  = {(const float*)d_in[3],  (const float*)d_in[9],  (const float*)d_in[15]};
    const float* as_[3]= {(const float*)d_in[4],  (const float*)d_in[10], (const float*)d_in[16]};
    const float* ad_[3]= {(const float*)d_in[5],  (const float*)d_in[11], (const float*)d_in[17]};
    const float* b_[3] = {(const float*)d_in[6],  (const float*)d_in[12], (const float*)d_in[18]};
    const float* gm_[3]= {(const float*)d_in[7],  (const float*)d_in[13], (const float*)d_in[19]};
    const float* be_[3]= {(const float*)d_in[8],  (const float*)d_in[14], (const float*)d_in[20]};
    const float* fcW = (const float*)d_in[21];
    const float* fcb = (const float*)d_in[22];
    float* out = (float*)d_out;

    // one-time infra (host resources only; graph topology identical every call)
    static cudaStream_t s2 = nullptr;
    static cudaEvent_t evF = nullptr, evW = nullptr, evC = nullptr;
    if (s2 == nullptr) {
        cudaStreamCreateWithFlags(&s2, cudaStreamNonBlocking);
        cudaEventCreateWithFlags(&evF, cudaEventDisableTiming);
        cudaEventCreateWithFlags(&evW, cudaEventDisableTiming);
        cudaEventCreateWithFlags(&evC, cudaEventDisableTiming);
        cudaFuncSetAttribute(k_mma, cudaFuncAttributeMaxDynamicSharedMemorySize, MMA_SMEM);
    }

    dim3 gemm_grid(4, (NN + 63) / 64);   // 4 x 313 = 1252 tiles

    // fork: side stream does W-split + CSR build concurrently with A-split + mma0
    cudaEventRecord(evF, 0);
    cudaStreamWaitEvent(s2, evF, 0);

    k_split_a<<<2560, 256>>>(x);                                        // main #1
    k_split_w3<<<(3 * DD * DD + 511) / 512, 512, 0, s2>>>(W[0], W[1], W[2]); // s2 #2
    cudaEventRecord(evW, s2);
    k_init<<<(NN + 255) / 256, 256, 0, s2>>>();                         // s2 #3
    cudaStreamWaitEvent(0, evW, 0);                 // mma0 needs W splits
    k_mma<<<gemm_grid, 128, MMA_SMEM>>>(as_[0], ad_[0], 0);             // main #4 <- profiled
    k_countinfo<<<(ETOT + 255) / 256, 256, 0, s2>>>(ei, batch);         // s2
    k_scan<<<1, SCAN_T, 0, s2>>>();                                     // s2
    k_fill<<<(ETOT + 255) / 256, 256, 0, s2>>>(ei);                     // s2
    cudaEventRecord(evC, s2);
    cudaStreamWaitEvent(0, evC, 0);                 // aggregate needs CSR

    k_aggregate<<<NN / 8, 256>>>(b_[0], gm_[0], be_[0], 0);

    for (int l = 1; l < 3; l++) {
        k_mma<<<gemm_grid, 128, MMA_SMEM>>>(as_[l], ad_[l], l);
        k_aggregate<<<NN / 8, 256>>>(b_[l], gm_[l], be_[l], l == 2 ? 1 : 0);
    }

    k_poolfc<<<GG, 128>>>(fcW, fcb, out);
}